// round 6
// baseline (speedup 1.0000x reference)
#include <cuda_runtime.h>
#include <cuda_fp16.h>
#include <math.h>
#include <stdint.h>

#define NTOK 4096
#define DDIM 1024
#define HDIM 4096
#define NEXP 8
#define NGRP 9
#define SBASE (2 * NTOK)
#define AROWS (3 * NTOK)
#define NPERS 304          // persistent CTAs (2 per SM x 152 SMs on GB300)

// ---------------------------------------------------------------------------
// Device-global scratch
// ---------------------------------------------------------------------------
__device__ __half g_xa [(size_t)AROWS * DDIM];   // gathered A (fp16)
__device__ __half g_h  [(size_t)AROWS * HDIM];   // hidden acts (fp16)
__device__ float  g_y  [(size_t)AROWS * DDIM];   // phase-2 out (pre-combine)
__device__ int    g_tok [NEXP * NTOK];
__device__ int    g_cnt [NEXP];
__device__ int    g_base[NGRP];
__device__ int    g_stok[SBASE];
__device__ int    g_te  [2 * NTOK];
__device__ int    g_tp  [2 * NTOK];
__device__ float  g_tw  [2 * NTOK];
__device__ float  g_imp [NEXP];
__device__ int    g_load[NEXP];
__device__ int    g_toff1[NGRP + 1];
__device__ int    g_toff2[NGRP + 1];

// ---------------------------------------------------------------------------
// PTX helpers
// ---------------------------------------------------------------------------
__device__ __forceinline__ void cp_async16(uint32_t s, const void* g) {
    asm volatile("cp.async.cg.shared.global [%0], [%1], 16;\n" :: "r"(s), "l"(g));
}
__device__ __forceinline__ void cp_commit() { asm volatile("cp.async.commit_group;\n"); }
template <int NN> __device__ __forceinline__ void cp_wait() {
    asm volatile("cp.async.wait_group %0;\n" :: "n"(NN));
}
__device__ __forceinline__ void ldsm4(uint32_t* r, uint32_t addr) {
    asm volatile("ldmatrix.sync.aligned.m8n8.x4.shared.b16 {%0,%1,%2,%3}, [%4];\n"
                 : "=r"(r[0]), "=r"(r[1]), "=r"(r[2]), "=r"(r[3]) : "r"(addr));
}
__device__ __forceinline__ void ldsm4t(uint32_t* r, uint32_t addr) {
    asm volatile("ldmatrix.sync.aligned.m8n8.x4.trans.shared.b16 {%0,%1,%2,%3}, [%4];\n"
                 : "=r"(r[0]), "=r"(r[1]), "=r"(r[2]), "=r"(r[3]) : "r"(addr));
}
__device__ __forceinline__ void mma_m16n8k16(float* c, const uint32_t* a, const uint32_t* b) {
    asm volatile(
        "mma.sync.aligned.m16n8k16.row.col.f32.f16.f16.f32 "
        "{%0,%1,%2,%3}, {%4,%5,%6,%7}, {%8,%9}, {%0,%1,%2,%3};\n"
        : "+f"(c[0]), "+f"(c[1]), "+f"(c[2]), "+f"(c[3])
        : "r"(a[0]), "r"(a[1]), "r"(a[2]), "r"(a[3]), "r"(b[0]), "r"(b[1]));
}
__device__ __forceinline__ float gelu_exact(float v) {
    return 0.5f * v * (1.0f + erff(v * 0.70710678118654752440f));
}

// ---------------------------------------------------------------------------
// Setup / routing kernels
// ---------------------------------------------------------------------------
__global__ void init_kernel() {
    int t = threadIdx.x;
    if (t < NEXP) { g_cnt[t] = 0; g_imp[t] = 0.f; g_load[t] = 0; }
}

__global__ void gating_kernel(const float* __restrict__ x,
                              const float* __restrict__ gw,
                              const float* __restrict__ gb) {
    __shared__ float s_imp[NEXP];
    __shared__ int   s_load[NEXP];
    int tid = threadIdx.x;
    if (tid < NEXP) { s_imp[tid] = 0.f; s_load[tid] = 0; }
    __syncthreads();

    int token = blockIdx.x * 8 + (tid >> 5);
    int lane  = tid & 31;

    float acc[NEXP];
#pragma unroll
    for (int e = 0; e < NEXP; e++) acc[e] = 0.f;

    const float* xr = x + (size_t)token * DDIM;
    for (int d = lane; d < DDIM; d += 32) {
        float xv = xr[d];
        const float4* gr = reinterpret_cast<const float4*>(gw + (size_t)d * NEXP);
        float4 g0 = gr[0], g1 = gr[1];
        acc[0] += xv * g0.x; acc[1] += xv * g0.y; acc[2] += xv * g0.z; acc[3] += xv * g0.w;
        acc[4] += xv * g1.x; acc[5] += xv * g1.y; acc[6] += xv * g1.z; acc[7] += xv * g1.w;
    }
#pragma unroll
    for (int e = 0; e < NEXP; e++) {
#pragma unroll
        for (int off = 16; off; off >>= 1)
            acc[e] += __shfl_xor_sync(0xffffffffu, acc[e], off);
    }

    if (lane == 0) {
        float l[NEXP];
        float mx = -1e30f;
#pragma unroll
        for (int e = 0; e < NEXP; e++) { l[e] = acc[e] + gb[e]; mx = fmaxf(mx, l[e]); }
        float p[NEXP], s = 0.f;
#pragma unroll
        for (int e = 0; e < NEXP; e++) { p[e] = expf(l[e] - mx); s += p[e]; }
        float inv = 1.f / s;
#pragma unroll
        for (int e = 0; e < NEXP; e++) atomicAdd(&s_imp[e], p[e] * inv);

        int i0 = 0;
#pragma unroll
        for (int e = 1; e < NEXP; e++) if (l[e] > l[i0]) i0 = e;
        int i1 = (i0 == 0) ? 1 : 0;
#pragma unroll
        for (int e = 0; e < NEXP; e++) if (e != i0 && l[e] > l[i1]) i1 = e;

        float w0 = 1.f / (1.f + expf(l[i1] - l[i0]));
        float w1 = 1.f - w0;

        int p0 = atomicAdd(&g_cnt[i0], 1);
        g_tok[i0 * NTOK + p0] = token;
        g_te[2 * token] = i0; g_tp[2 * token] = p0; g_tw[2 * token] = w0;
        int p1 = atomicAdd(&g_cnt[i1], 1);
        g_tok[i1 * NTOK + p1] = token;
        g_te[2 * token + 1] = i1; g_tp[2 * token + 1] = p1; g_tw[2 * token + 1] = w1;
        atomicAdd(&s_load[i0], 1);
        atomicAdd(&s_load[i1], 1);
    }
    __syncthreads();
    if (tid < NEXP) {
        atomicAdd(&g_imp[tid], s_imp[tid]);
        atomicAdd(&g_load[tid], s_load[tid]);
    }
}

__global__ void prefix_kernel() {
    if (threadIdx.x == 0) {
        int s = 0;
#pragma unroll
        for (int e = 0; e < NEXP; e++) { g_base[e] = s; s += g_cnt[e]; }
        g_base[NEXP] = s;
        int o1 = 0, o2 = 0;
#pragma unroll
        for (int g = 0; g < NGRP; g++) {
            int mt = (g < NEXP) ? ((g_cnt[g] + 127) >> 7) : (NTOK >> 7);
            g_toff1[g] = o1; o1 += mt * (HDIM / 128);
            g_toff2[g] = o2; o2 += mt * (DDIM / 128);
        }
        g_toff1[NGRP] = o1;
        g_toff2[NGRP] = o2;
    }
}

__global__ void slotmap_kernel() {
    int e = blockIdx.x;
    int b = g_base[e], n = g_cnt[e];
    for (int i = threadIdx.x; i < n; i += blockDim.x)
        g_stok[b + i] = g_tok[e * NTOK + i];
}

__global__ void gather_kernel(const float* __restrict__ x) {
    int r = blockIdx.x;
    int tok = (r < SBASE) ? g_stok[r] : (r - SBASE);
    const float4* src = reinterpret_cast<const float4*>(x + (size_t)tok * DDIM);
    uint4* dst = reinterpret_cast<uint4*>(g_xa + (size_t)r * DDIM);
    int t = threadIdx.x;
    float4 a = src[2 * t], b = src[2 * t + 1];
    __half2 h0 = __floats2half2_rn(a.x, a.y);
    __half2 h1 = __floats2half2_rn(a.z, a.w);
    __half2 h2 = __floats2half2_rn(b.x, b.y);
    __half2 h3 = __floats2half2_rn(b.z, b.w);
    uint4 o;
    o.x = *reinterpret_cast<uint32_t*>(&h0);
    o.y = *reinterpret_cast<uint32_t*>(&h1);
    o.z = *reinterpret_cast<uint32_t*>(&h2);
    o.w = *reinterpret_cast<uint32_t*>(&h3);
    dst[t] = o;
}

// ---------------------------------------------------------------------------
// Persistent fp16 mma GEMM with fused fp32->fp16 B conversion.
// Tile 128x128x32. 8 warps. 4-stage cp.async ring:
//   A (fp16, swizzled, 8 KB/stage) + B staging (fp32, 16 KB/stage)
// B converted staging->f16 buf (8 KB, XOR swizzle) on idle LSU/ALU pipes.
// PHASE 1: g_h = gelu(g_xa @ w1[g] + b1)   PHASE 2: g_y = g_h @ w2[g] + b2
// ---------------------------------------------------------------------------
#define SM_A_OFF   0
#define SM_A_STG   8192
#define SM_STG_OFF (4 * SM_A_STG)            // 32768
#define SM_STG_STG 16384
#define SM_B16_OFF (SM_STG_OFF + 4 * SM_STG_STG)  // 98304
#define SMEM_GEMM  (SM_B16_OFF + 8192)       // 106496

template <int PHASE>
__global__ void __launch_bounds__(256, 2) moe_gemm(
    const float* __restrict__ W_e,    // w1 [E,D,H] or w2 [E,H,D] (fp32)
    const float* __restrict__ W_s,    // sw1 [D,H] or sw2 [H,D]
    const float* __restrict__ bias_e,
    const float* __restrict__ bias_s) {
    constexpr int KDIM   = (PHASE == 1) ? DDIM : HDIM;
    constexpr int LDB    = (PHASE == 1) ? HDIM : DDIM;
    constexpr int KT     = KDIM / 32;
    constexpr int NSHIFT = (PHASE == 1) ? 5 : 3;      // ntiles = 32 or 8
    constexpr int NTILES = 1 << NSHIFT;

    extern __shared__ __align__(16) char smem[];
    const uint32_t sm32 = (uint32_t)__cvta_generic_to_shared(smem);

    const int tid  = threadIdx.x;
    const int lane = tid & 31;
    const int warp = tid >> 5;
    const int wm   = warp >> 1;
    const int wn   = warp & 1;

    int toff[NGRP + 1];
#pragma unroll
    for (int g = 0; g <= NGRP; g++)
        toff[g] = (PHASE == 1) ? g_toff1[g] : g_toff2[g];
    const int total = toff[NGRP];

    // precomputed per-thread load indices
    // A: 2 chunks: idx = tid + 256j -> r = idx>>2 (0..127), kc = idx&3
    // B: 4 chunks: idx = tid + 256j -> row = idx>>5 (0..31), f4 = idx&31
    const int a_r[2]  = { tid >> 2, (tid >> 2) + 64 };
    const int a_kc    = tid & 3;
    const int b_row   = tid >> 5;      // j adds 8 rows
    const int b_f4    = tid & 31;

    for (int idx = blockIdx.x; idx < total; idx += gridDim.x) {
        int g = 0;
#pragma unroll
        for (int q = 1; q < NGRP; q++) g += (idx >= toff[q]);
        const int rem = idx - toff[g];
        const int m0  = (rem >> NSHIFT) * 128;
        const int n0  = (rem & (NTILES - 1)) * 128;
        const int cnt  = (g == NEXP) ? NTOK : g_cnt[g];
        const int base = g_base[g];

        const float* __restrict__ Bp =
            (g < NEXP) ? W_e + (size_t)g * DDIM * HDIM : W_s;
        const float* __restrict__ bias =
            (g < NEXP) ? bias_e + (size_t)g * LDB : bias_s;
        const __half* __restrict__ Ap =
            ((PHASE == 1) ? g_xa : g_h) + (size_t)(base + m0) * KDIM;

        __syncthreads();   // protect smem reuse across tiles

        auto load_stage = [&](int kt) {
            const int s = kt & 3;
            const int k0 = kt * 32;
            // A fp16: 2 x 16B chunks
#pragma unroll
            for (int j = 0; j < 2; j++) {
                int r = a_r[j];
                uint32_t pch = ((uint32_t)(a_kc + ((r >> 6) << 2))) ^ (uint32_t)(r & 7);
                cp_async16(sm32 + SM_A_OFF + s * SM_A_STG + (r & 63) * 128 + pch * 16,
                           Ap + (size_t)r * KDIM + k0 + a_kc * 8);
            }
            // B fp32 staging: 4 x 16B chunks
#pragma unroll
            for (int j = 0; j < 4; j++) {
                int row = b_row + j * 8;
                cp_async16(sm32 + SM_STG_OFF + s * SM_STG_STG + row * 512 + b_f4 * 16,
                           Bp + (size_t)(k0 + row) * LDB + n0 + b_f4 * 4);
            }
            cp_commit();
        };

        load_stage(0); load_stage(1); load_stage(2);

        float acc[2][8][4] = {};

        for (int kt = 0; kt < KT; kt++) {
            if (kt + 2 < KT)      cp_wait<2>();
            else if (kt + 1 < KT) cp_wait<1>();
            else                  cp_wait<0>();
            __syncthreads();   // stage kt visible; prev iter consumers done

            if (kt + 3 < KT) load_stage(kt + 3);

            // convert B staging (fp32) -> f16 buffer (XOR swizzle)
            {
                const int s = kt & 3;
                const char* stg = smem + SM_STG_OFF + s * SM_STG_STG;
#pragma unroll
                for (int j = 0; j < 4; j++) {
                    int row = b_row + j * 8;
                    const float4 v = *reinterpret_cast<const float4*>(
                        stg + row * 512 + b_f4 * 16);
                    __half2 h0 = __floats2half2_rn(v.x, v.y);
                    __half2 h1 = __floats2half2_rn(v.z, v.w);
                    uint2 o;
                    o.x = *reinterpret_cast<uint32_t*>(&h0);
                    o.y = *reinterpret_cast<uint32_t*>(&h1);
                    uint32_t nc = ((uint32_t)(b_f4 >> 1)) ^ (uint32_t)(row & 7);
                    *reinterpret_cast<uint2*>(
                        smem + SM_B16_OFF + row * 256 + nc * 16 + (b_f4 & 1) * 8) = o;
                }
            }
            __syncthreads();   // f16B ready for all warps

            const int s = kt & 3;
            const uint32_t ab = sm32 + SM_A_OFF + s * SM_A_STG;
            const uint32_t bb = sm32 + SM_B16_OFF;

#pragma unroll
            for (int ks = 0; ks < 2; ks++) {
                uint32_t a[2][4], b[4][4];
#pragma unroll
                for (int mt = 0; mt < 2; mt++) {
                    int r  = wm * 32 + mt * 16 + (lane & 15);
                    int kc = ks * 2 + (lane >> 4);
                    uint32_t pch = ((uint32_t)(kc + ((r >> 6) << 2))) ^ (uint32_t)(r & 7);
                    ldsm4(a[mt], ab + (r & 63) * 128 + pch * 16);
                }
#pragma unroll
                for (int np = 0; np < 4; np++) {
                    int row  = ks * 16 + (lane & 15);
                    int ncol = wn * 64 + np * 16 + ((lane >> 4) << 3);
                    uint32_t nc = ((uint32_t)(ncol >> 3)) ^ (uint32_t)(row & 7);
                    ldsm4t(b[np], bb + row * 256 + nc * 16);
                }
#pragma unroll
                for (int mt = 0; mt < 2; mt++)
#pragma unroll
                    for (int nt = 0; nt < 8; nt++)
                        mma_m16n8k16(acc[mt][nt], a[mt], &b[nt >> 1][(nt & 1) * 2]);
            }
        }

        // Epilogue
        const int lr = lane >> 2;
        const int lc = (lane & 3) * 2;
#pragma unroll
        for (int mt = 0; mt < 2; mt++) {
#pragma unroll
            for (int hh = 0; hh < 2; hh++) {
                int m = m0 + wm * 32 + mt * 16 + lr + hh * 8;
                if (m < cnt) {
                    if (PHASE == 1) {
                        __half* hp = g_h + (size_t)(base + m) * HDIM;
#pragma unroll
                        for (int nt = 0; nt < 8; nt++) {
                            int n = n0 + wn * 64 + nt * 8 + lc;
                            float v0 = gelu_exact(acc[mt][nt][hh * 2 + 0] + bias[n]);
                            float v1 = gelu_exact(acc[mt][nt][hh * 2 + 1] + bias[n + 1]);
                            *reinterpret_cast<__half2*>(hp + n) = __floats2half2_rn(v0, v1);
                        }
                    } else {
                        float* yp = g_y + (size_t)(base + m) * DDIM;
#pragma unroll
                        for (int nt = 0; nt < 8; nt++) {
                            int n = n0 + wn * 64 + nt * 8 + lc;
                            float2 v;
                            v.x = acc[mt][nt][hh * 2 + 0] + bias[n];
                            v.y = acc[mt][nt][hh * 2 + 1] + bias[n + 1];
                            *reinterpret_cast<float2*>(yp + n) = v;
                        }
                    }
                }
            }
        }
    }
}

// ---------------------------------------------------------------------------
// Combine + finalize
// ---------------------------------------------------------------------------
__global__ void combine_kernel(float* __restrict__ out) {
    int t = blockIdx.x;
    int e0 = g_te[2 * t],   e1 = g_te[2 * t + 1];
    float w0 = g_tw[2 * t], w1 = g_tw[2 * t + 1];
    size_t s0 = (size_t)(g_base[e0] + g_tp[2 * t]);
    size_t s1 = (size_t)(g_base[e1] + g_tp[2 * t + 1]);
    const float4* y0 = reinterpret_cast<const float4*>(g_y + s0 * DDIM);
    const float4* y1 = reinterpret_cast<const float4*>(g_y + s1 * DDIM);
    const float4* ys = reinterpret_cast<const float4*>(g_y + (size_t)(SBASE + t) * DDIM);
    float4* op = reinterpret_cast<float4*>(out + (size_t)t * DDIM);
    int i = threadIdx.x;
    float4 a = y0[i], b = y1[i], c = ys[i];
    float4 o;
    o.x = w0 * a.x + w1 * b.x + c.x;
    o.y = w0 * a.y + w1 * b.y + c.y;
    o.z = w0 * a.z + w1 * b.z + c.z;
    o.w = w0 * a.w + w1 * b.w + c.w;
    op[i] = o;
}

__global__ void finalize_kernel(float* __restrict__ out, int out_size) {
    if (threadIdx.x == 0 && blockIdx.x == 0) {
        float si = 0.f, sl = 0.f, imp[NEXP], ld[NEXP];
#pragma unroll
        for (int e = 0; e < NEXP; e++) {
            imp[e] = g_imp[e]; ld[e] = (float)g_load[e];
            si += imp[e]; sl += ld[e];
        }
        float a = 0.f;
#pragma unroll
        for (int e = 0; e < NEXP; e++) {
            float d = imp[e] / (si + 1e-8f) - ld[e] / (sl + 1e-8f);
            a += d * d;
        }
        out[out_size - 1] = a;
    }
}

// ---------------------------------------------------------------------------
// Launch
// ---------------------------------------------------------------------------
extern "C" void kernel_launch(void* const* d_in, const int* in_sizes, int n_in,
                              void* d_out, int out_size) {
    const float* x      = (const float*)d_in[0];
    const float* gate_w = (const float*)d_in[1];
    const float* gate_b = (const float*)d_in[2];
    const float* w1     = (const float*)d_in[3];
    const float* b1     = (const float*)d_in[4];
    const float* w2     = (const float*)d_in[5];
    const float* b2     = (const float*)d_in[6];
    const float* sw1    = (const float*)d_in[7];
    const float* sb1    = (const float*)d_in[8];
    const float* sw2    = (const float*)d_in[9];
    const float* sb2    = (const float*)d_in[10];
    float* out = (float*)d_out;

    cudaFuncSetAttribute(moe_gemm<1>, cudaFuncAttributeMaxDynamicSharedMemorySize, SMEM_GEMM);
    cudaFuncSetAttribute(moe_gemm<2>, cudaFuncAttributeMaxDynamicSharedMemorySize, SMEM_GEMM);

    init_kernel<<<1, 32>>>();
    gating_kernel<<<NTOK / 8, 256>>>(x, gate_w, gate_b);
    prefix_kernel<<<1, 32>>>();
    slotmap_kernel<<<NEXP, 256>>>();
    gather_kernel<<<AROWS, 128>>>(x);

    moe_gemm<1><<<NPERS, 256, SMEM_GEMM>>>(w1, sw1, b1, sb1);
    moe_gemm<2><<<NPERS, 256, SMEM_GEMM>>>(w2, sw2, b2, sb2);

    combine_kernel<<<NTOK, 256>>>(out);
    finalize_kernel<<<1, 32>>>(out, out_size);
}